// round 15
// baseline (speedup 1.0000x reference)
#include <cuda_runtime.h>
#include <cuda_fp16.h>
#include <cstdint>
#include <math.h>

#define BATCH 8
#define DIM   512
#define HW    4096
#define IDIM  256

typedef __half fp16;

// ---------------- device scratch (static) ----------------
__device__ fp16  g_QKh[(size_t)BATCH * HW * 512];    // raw [phi;theta] fp16 from k1
__device__ fp16  g_Eh[(size_t)BATCH * HW * HW];      // exp(scores), single fp16 plane
__device__ float g_part[(size_t)BATCH * HW * 32];    // per-CTA row partials (reused)
__device__ float g_inv[(size_t)BATCH * HW];          // 1 / rowsum
__device__ fp16  g_Fth[(size_t)BATCH * HW * DIM];    // F^T [b][n][c], 1 plane
__device__ fp16  g_Fh[(size_t)BATCH * DIM * HW];     // F [b][c][m], 1 plane
__device__ fp16  g_Qh[(size_t)BATCH * HW * IDIM];    // normalized phi (pre-scaled by log2e)
__device__ fp16  g_Kh[(size_t)BATCH * HW * IDIM];    // normalized theta
__device__ fp16  g_Mh[(size_t)BATCH * HW * DIM];     // attn out [b][n][c]
__device__ fp16  g_Wth[(size_t)DIM * DIM];           // W^T [d][c], 1 plane
__device__ fp16  g_PTh[(size_t)2 * IDIM * DIM];      // stacked [phi_w; theta_w]

// ---------------- helpers ----------------
__device__ __forceinline__ uint32_t smem_u32(const void* p) {
    uint32_t a;
    asm("{ .reg .u64 t; cvta.to.shared.u64 t, %1; cvt.u32.u64 %0, t; }" : "=r"(a) : "l"(p));
    return a;
}
__device__ __forceinline__ void cp16(uint32_t d, const void* s) {
    asm volatile("cp.async.cg.shared.global [%0], [%1], 16;" :: "r"(d), "l"(s));
}

#define LDSM4(R, addr)                                                           \
    asm volatile("ldmatrix.sync.aligned.m8n8.x4.shared.b16 {%0,%1,%2,%3}, [%4];" \
        : "=r"((R)[0]), "=r"((R)[1]), "=r"((R)[2]), "=r"((R)[3]) : "r"(addr))

#define MMA_FP16(c, a, b0, b1)                                                   \
    asm volatile(                                                                \
        "mma.sync.aligned.m16n8k16.row.col.f32.f16.f16.f32 "                     \
        "{%0,%1,%2,%3}, {%4,%5,%6,%7}, {%8,%9}, {%0,%1,%2,%3};"                  \
        : "+f"((c)[0]), "+f"((c)[1]), "+f"((c)[2]), "+f"((c)[3])                 \
        : "r"((a)[0]), "r"((a)[1]), "r"((a)[2]), "r"((a)[3]),                    \
          "r"((b0)), "r"((b1)))

// BK=32: rows are 64B (4 x 16B granules). granule q of row r stored at q ^ ((r>>1)&3).
// Stage: A (128 rows, 8KB) at 0, B (256 rows, 16KB) at 8192. SPS = 24576, 4 stages.
#define SPS 24576
__device__ __forceinline__ void fill_A(uint32_t dbase, const fp16* src, int Kdim, int tid) {
    int row = tid >> 2, q = tid & 3;        // 512 threads cover 128 rows x 4
    cp16(dbase + row * 64 + ((q ^ ((row >> 1) & 3)) << 4),
         src + (size_t)row * Kdim + q * 8);
}
__device__ __forceinline__ void fill_B(uint32_t dbase, const fp16* src, int Kdim, int tid) {
    #pragma unroll
    for (int t = 0; t < 2; t++) {           // 256 rows x 4
        int idx = tid + t * 512;
        int row = idx >> 2, q = idx & 3;
        cp16(dbase + row * 64 + ((q ^ ((row >> 1) & 3)) << 4),
             src + (size_t)row * Kdim + q * 8);
    }
}

// ================= fp16 NT GEMM via mma.sync + ldmatrix =================
// C[m][n] = sum_k A[m][k]*B[n][k].  CTA 128x256, 16 warps (2x8) of 64x32 each,
// BK=32, 4-stage cp.async pipeline, ONE __syncthreads per K-chunk.
// MODE 0: fp32 store   1: relu fp32 store
// MODE 3: exp2() + fp16 store + row partial sums (k2; Q pre-scaled by log2e)
// MODE 4: row scale by Inv + fp16 store (k4)
// MODE 5: fp16 store + row partial sum-of-squares (k1)
template<int MODE>
__global__ void __launch_bounds__(512) gemm_fp16(
    const fp16* __restrict__ A, const fp16* __restrict__ B,
    float* __restrict__ C, fp16* __restrict__ Ch,
    float* __restrict__ Part, const float* __restrict__ Inv,
    int Kdim, int Ncols, size_t sA, size_t sB, size_t sC)
{
    extern __shared__ char smem[];
    const int tid  = threadIdx.x;
    const int lane = tid & 31, wid = tid >> 5;
    const int g = lane >> 2, tg = lane & 3;
    const int wm = wid >> 3, wn = wid & 7;
    const uint32_t sb = smem_u32(smem);

    const fp16* pA = A + blockIdx.z * sA + (size_t)blockIdx.y * 128 * Kdim;
    const fp16* pB = B + blockIdx.z * sB + (size_t)blockIdx.x * 256 * Kdim;

    float acc[4][4][4];
    #pragma unroll
    for (int i = 0; i < 4; i++)
        #pragma unroll
        for (int j = 0; j < 4; j++)
            #pragma unroll
            for (int e = 0; e < 4; e++) acc[i][j][e] = 0.f;

    const int NC = Kdim >> 5;
    const int rb = lane & 15, gs = lane >> 4;
    const int swz = (rb >> 1) & 3;

    // prologue: fill stages 0,1
    fill_A(sb, pA, Kdim, tid);
    fill_B(sb + 8192, pB, Kdim, tid);
    asm volatile("cp.async.commit_group;");
    fill_A(sb + SPS, pA + 32, Kdim, tid);
    fill_B(sb + SPS + 8192, pB + 32, Kdim, tid);
    asm volatile("cp.async.commit_group;");

    for (int c = 0; c < NC; c++) {
        if (c + 2 < NC) {
            uint32_t nb = sb + ((c + 2) & 3) * SPS;
            int ko = (c + 2) * 32;
            fill_A(nb, pA + ko, Kdim, tid);
            fill_B(nb + 8192, pB + ko, Kdim, tid);
            asm volatile("cp.async.commit_group;");
            asm volatile("cp.async.wait_group 2;");
        } else if (c + 2 == NC) {
            asm volatile("cp.async.wait_group 1;");
        } else {
            asm volatile("cp.async.wait_group 0;");
        }
        __syncthreads();   // the ONLY barrier per chunk

        uint32_t bb = sb + (c & 3) * SPS;
        #pragma unroll
        for (int s = 0; s < 2; s++) {
            const int gp = (((2 * s + gs) ^ swz) << 4);
            uint32_t af[4][4], bf[2][4];
            #pragma unroll
            for (int i = 0; i < 4; i++) {
                uint32_t ra = bb + (uint32_t)(wm * 64 + i * 16 + rb) * 64 + gp;
                LDSM4(af[i], ra);
            }
            #pragma unroll
            for (int t = 0; t < 2; t++) {
                uint32_t rba = bb + 8192 + (uint32_t)(wn * 32 + t * 16 + rb) * 64 + gp;
                LDSM4(bf[t], rba);
            }
            #pragma unroll
            for (int i = 0; i < 4; i++)
                #pragma unroll
                for (int j = 0; j < 4; j++) {
                    const int t = j >> 1, u = j & 1;
                    MMA_FP16(acc[i][j], af[i], bf[t][u], bf[t][u + 2]);
                }
        }
    }

    // ---------------- epilogue ----------------
    const int row0 = blockIdx.y * 128 + wm * 64;
    const int col0 = blockIdx.x * 256 + wn * 32;
    const int bz = blockIdx.z;

    if (MODE == 3 || MODE == 5) {
        __syncthreads();               // spart aliases stage 0
        float* spart = (float*)smem;   // [128][8]
        float rsum[4][2];
        #pragma unroll
        for (int i = 0; i < 4; i++) { rsum[i][0] = 0.f; rsum[i][1] = 0.f; }
        #pragma unroll
        for (int i = 0; i < 4; i++) {
            int r0 = row0 + i * 16 + g;
            #pragma unroll
            for (int j = 0; j < 4; j++) {
                int cc = col0 + j * 8 + tg * 2;
                float e0 = acc[i][j][0], e1 = acc[i][j][1];
                float e2 = acc[i][j][2], e3 = acc[i][j][3];
                if (MODE == 3) {
                    e0 = exp2f(e0); e1 = exp2f(e1);
                    e2 = exp2f(e2); e3 = exp2f(e3);
                    rsum[i][0] += e0 + e1;
                    rsum[i][1] += e2 + e3;
                } else {
                    rsum[i][0] += e0 * e0 + e1 * e1;
                    rsum[i][1] += e2 * e2 + e3 * e3;
                }
                size_t o0 = bz * sC + (size_t)r0 * Ncols + cc;
                size_t o1 = o0 + 8 * (size_t)Ncols;
                __half2 p0; p0.x = __float2half_rn(e0); p0.y = __float2half_rn(e1);
                __half2 p1; p1.x = __float2half_rn(e2); p1.y = __float2half_rn(e3);
                *reinterpret_cast<__half2*>(Ch + o0) = p0;
                *reinterpret_cast<__half2*>(Ch + o1) = p1;
            }
        }
        #pragma unroll
        for (int i = 0; i < 4; i++) {
            #pragma unroll
            for (int h = 0; h < 2; h++) {
                float v = rsum[i][h];
                v += __shfl_xor_sync(0xffffffffu, v, 1);
                v += __shfl_xor_sync(0xffffffffu, v, 2);
                if (tg == 0)
                    spart[(wm * 64 + i * 16 + g + h * 8) * 8 + wn] = v;
            }
        }
        __syncthreads();
        if (tid < 128) {
            float4 p0 = *reinterpret_cast<float4*>(spart + tid * 8);
            float4 p1 = *reinterpret_cast<float4*>(spart + tid * 8 + 4);
            Part[((size_t)bz * HW + blockIdx.y * 128 + tid) * gridDim.x + blockIdx.x] =
                p0.x + p0.y + p0.z + p0.w + p1.x + p1.y + p1.z + p1.w;
        }
        return;
    }

    #pragma unroll
    for (int i = 0; i < 4; i++) {
        int r0 = row0 + i * 16 + g;
        float inv0 = 1.f, inv1 = 1.f;
        if (MODE == 4) {
            inv0 = Inv[(size_t)bz * HW + r0];
            inv1 = Inv[(size_t)bz * HW + r0 + 8];
        }
        #pragma unroll
        for (int j = 0; j < 4; j++) {
            int cc = col0 + j * 8 + tg * 2;
            if (MODE == 4) {
                size_t o0 = bz * sC + (size_t)r0 * Ncols + cc;
                size_t o1 = o0 + 8 * (size_t)Ncols;
                __half2 p0, p1;
                p0.x = __float2half_rn(acc[i][j][0] * inv0);
                p0.y = __float2half_rn(acc[i][j][1] * inv0);
                p1.x = __float2half_rn(acc[i][j][2] * inv1);
                p1.y = __float2half_rn(acc[i][j][3] * inv1);
                *reinterpret_cast<__half2*>(Ch + o0) = p0;
                *reinterpret_cast<__half2*>(Ch + o1) = p1;
            } else {
                float* b0 = C + bz * sC + (size_t)r0 * Ncols + cc;
                float* b1 = b0 + 8 * (size_t)Ncols;
                float2 v0, v1;
                v0.x = acc[i][j][0]; v0.y = acc[i][j][1];
                v1.x = acc[i][j][2]; v1.y = acc[i][j][3];
                if (MODE == 1) {
                    v0.x = fmaxf(v0.x, 0.f); v0.y = fmaxf(v0.y, 0.f);
                    v1.x = fmaxf(v1.x, 0.f); v1.y = fmaxf(v1.y, 0.f);
                }
                *reinterpret_cast<float2*>(b0) = v0;
                *reinterpret_cast<float2*>(b1) = v1;
            }
        }
    }
}

// ---------------- inv rowsum (k2 partials, 16 per row) ----------------
__global__ void __launch_bounds__(256) k3b_inv() {
    int wid = threadIdx.x >> 5, lane = threadIdx.x & 31;
    size_t rr = (size_t)blockIdx.x * 8 + wid;
    float v = (lane < 16) ? g_part[rr * 16 + lane] : 0.f;
    #pragma unroll
    for (int o = 8; o > 0; o >>= 1) v += __shfl_xor_sync(0xffffffffu, v, o);
    v += __shfl_xor_sync(0xffffffffu, v, 16);
    if (lane == 0) g_inv[rr] = 1.0f / v;
}

// ---------------- normalize QKh rows -> Qh (x log2e), Kh (2 partials) ----------------
__global__ void __launch_bounds__(256) k1d_scale() {
    size_t row = blockIdx.x;
    __shared__ float sinv[2];
    int t = threadIdx.x;
    if (t == 0) {
        const float* p = g_part + row * 2;
        sinv[0] = rsqrtf(p[0]) * 1.4426950408889634f;  // phi (cols 0-255): fold log2e
        sinv[1] = rsqrtf(p[1]);                        // theta (cols 256-511)
    }
    __syncthreads();
    float s = sinv[t >> 7];
    __half2 v = reinterpret_cast<const __half2*>(g_QKh)[row * 256 + t];
    float2 f = __half22float2(v);
    __half2 r;
    r.x = __float2half_rn(f.x * s);
    r.y = __float2half_rn(f.y * s);
    if (t < 128)
        reinterpret_cast<__half2*>(g_Qh)[row * 128 + t] = r;
    else
        reinterpret_cast<__half2*>(g_Kh)[row * 128 + (t - 128)] = r;
}

// ---------------- feat -> Fth (transposed fp16) + Fh (straight fp16), one read ----------------
__global__ void __launch_bounds__(256) trans_dual(const float* __restrict__ in,
                                                  fp16* __restrict__ oth,
                                                  fp16* __restrict__ ostr,
                                                  int R, int C) {
    __shared__ float t[32][33];
    int b = blockIdx.z;
    const float* ib = in + (size_t)b * R * C;
    size_t ob = (size_t)b * R * C;
    int c0 = blockIdx.x * 32, r0 = blockIdx.y * 32;
    int x = threadIdx.x, y = threadIdx.y;
    #pragma unroll
    for (int i = 0; i < 32; i += 8) {
        float v = ib[(size_t)(r0 + y + i) * C + c0 + x];
        t[y + i][x] = v;
        ostr[ob + (size_t)(r0 + y + i) * C + c0 + x] = __float2half_rn(v);
    }
    __syncthreads();
    #pragma unroll
    for (int i = 0; i < 32; i += 8)
        oth[ob + (size_t)(c0 + y + i) * R + r0 + x] = __float2half_rn(t[x][y + i]);
}

// ---------------- transpose, 1-plane fp16 ----------------
__global__ void __launch_bounds__(256) trans1(const float* __restrict__ in,
                                              fp16* __restrict__ oh, int R, int C) {
    __shared__ float t[32][33];
    int b = blockIdx.z;
    const float* ib = in + (size_t)b * R * C;
    size_t ob = (size_t)b * R * C;
    int c0 = blockIdx.x * 32, r0 = blockIdx.y * 32;
    int x = threadIdx.x, y = threadIdx.y;
    #pragma unroll
    for (int i = 0; i < 32; i += 8)
        t[y + i][x] = ib[(size_t)(r0 + y + i) * C + c0 + x];
    __syncthreads();
    #pragma unroll
    for (int i = 0; i < 32; i += 8)
        oh[ob + (size_t)(c0 + y + i) * R + r0 + x] = __float2half_rn(t[x][y + i]);
}

// ---------------- elementwise fp16 conversion ----------------
__global__ void __launch_bounds__(256) conv1(const float* __restrict__ in,
                                             fp16* __restrict__ oh) {
    size_t i0 = ((size_t)blockIdx.x * 256 + threadIdx.x) * 4;
    float4 v = *reinterpret_cast<const float4*>(in + i0);
    __half2 a, b;
    a.x = __float2half_rn(v.x); a.y = __float2half_rn(v.y);
    b.x = __float2half_rn(v.z); b.y = __float2half_rn(v.w);
    *reinterpret_cast<__half2*>(oh + i0)     = a;
    *reinterpret_cast<__half2*>(oh + i0 + 2) = b;
}

// ---------------- launch ----------------
extern "C" void kernel_launch(void* const* d_in, const int* in_sizes, int n_in,
                              void* d_out, int out_size) {
    const float* feat    = (const float*)d_in[0];   // [8, 512, 64, 64]
    const float* phi_w   = (const float*)d_in[1];   // [256, 512]
    const float* theta_w = (const float*)d_in[2];   // [256, 512]
    const float* weight  = (const float*)d_in[3];   // [512, 512]
    float* out = (float*)d_out;                     // [8, 512, 64, 64]

    cudaFuncSetAttribute(gemm_fp16<5>, cudaFuncAttributeMaxDynamicSharedMemorySize, 4 * SPS);
    cudaFuncSetAttribute(gemm_fp16<3>, cudaFuncAttributeMaxDynamicSharedMemorySize, 4 * SPS);
    cudaFuncSetAttribute(gemm_fp16<4>, cudaFuncAttributeMaxDynamicSharedMemorySize, 4 * SPS);
    cudaFuncSetAttribute(gemm_fp16<1>, cudaFuncAttributeMaxDynamicSharedMemorySize, 4 * SPS);

    float *Part, *Inv;
    fp16 *QKh, *Eh, *Fth, *Fh, *Qh, *Kh, *Mh, *Wth, *PTh;
    cudaGetSymbolAddress((void**)&QKh,  g_QKh);
    cudaGetSymbolAddress((void**)&Part, g_part);
    cudaGetSymbolAddress((void**)&Inv,  g_inv);
    cudaGetSymbolAddress((void**)&Eh,   g_Eh);
    cudaGetSymbolAddress((void**)&Fth,  g_Fth);
    cudaGetSymbolAddress((void**)&Fh,   g_Fh);
    cudaGetSymbolAddress((void**)&Qh,   g_Qh);
    cudaGetSymbolAddress((void**)&Kh,   g_Kh);
    cudaGetSymbolAddress((void**)&Mh,   g_Mh);
    cudaGetSymbolAddress((void**)&Wth,  g_Wth);
    cudaGetSymbolAddress((void**)&PTh,  g_PTh);

    // prep: one pass over feat -> Fth + Fh; W^T; stacked projection weights
    trans_dual<<<dim3(HW / 32, DIM / 32, BATCH), dim3(32, 8)>>>(feat, Fth, Fh, DIM, HW);
    trans1<<<dim3(DIM / 32, DIM / 32, 1), dim3(32, 8)>>>(weight, Wth, DIM, DIM);
    conv1<<<(IDIM * DIM) / 1024, 256>>>(phi_w, PTh);
    conv1<<<(IDIM * DIM) / 1024, 256>>>(theta_w, PTh + (size_t)IDIM * DIM);

    // k1: QKh[n][j] = Ft[n][:] . [phi_w;theta_w][j][:] + per-half sumsq  (M=4096, N=512, K=512)
    gemm_fp16<5><<<dim3(512 / 256, HW / 128, BATCH), 512, 4 * SPS>>>(
        Fth, PTh, nullptr, QKh, Part, nullptr,
        DIM, 512, (size_t)HW * DIM, 0, (size_t)HW * 512);

    // normalize rows -> Qh (pre-scaled by log2e), Kh
    k1d_scale<<<BATCH * HW, 256>>>();

    // k2: E[n][m] = exp2(Qs . K) + row partial sums  (M=N=4096, K=256)
    gemm_fp16<3><<<dim3(HW / 256, HW / 128, BATCH), 512, 4 * SPS>>>(
        Qh, Kh, nullptr, Eh, Part, nullptr,
        IDIM, HW, (size_t)HW * IDIM, (size_t)HW * IDIM, (size_t)HW * HW);

    k3b_inv<<<HW * BATCH / 8, 256>>>();

    // k4: M[n][c] = (sum_m E[n][m] * F[c][m]) * inv[n]  (M=4096, N=512, K=4096)
    gemm_fp16<4><<<dim3(DIM / 256, HW / 128, BATCH), 512, 4 * SPS>>>(
        Eh, Fh, nullptr, Mh, nullptr, Inv,
        HW, DIM, (size_t)HW * HW, (size_t)DIM * HW, (size_t)HW * DIM);

    // k5: out[d][n] = relu(Wth[d][:] . Mh[n][:])   (M=512, N=4096, K=512)
    gemm_fp16<1><<<dim3(HW / 256, DIM / 128, BATCH), 512, 4 * SPS>>>(
        Wth, Mh, out, nullptr, nullptr, nullptr,
        DIM, HW, 0, (size_t)HW * DIM, (size_t)DIM * HW);
}

// round 16
// speedup vs baseline: 1.1610x; 1.1610x over previous
#include <cuda_runtime.h>
#include <cuda_fp16.h>
#include <cstdint>
#include <math.h>

#define BATCH 8
#define DIM   512
#define HW    4096
#define IDIM  256

typedef __half fp16;

// ---------------- device scratch (static) ----------------
__device__ fp16  g_QKh[(size_t)BATCH * HW * 512];    // raw [phi;theta] fp16 from k1
__device__ fp16  g_Eh[(size_t)BATCH * HW * HW];      // exp(scores), single fp16 plane
__device__ float g_part[(size_t)BATCH * HW * 32];    // per-CTA row partials (reused)
__device__ float g_inv[(size_t)BATCH * HW];          // 1 / rowsum
__device__ fp16  g_Fth[(size_t)BATCH * HW * DIM];    // F^T [b][n][c], 1 plane
__device__ fp16  g_Fh[(size_t)BATCH * DIM * HW];     // F [b][c][m], 1 plane
__device__ fp16  g_Qh[(size_t)BATCH * HW * IDIM];    // normalized phi (pre-scaled by log2e)
__device__ fp16  g_Kh[(size_t)BATCH * HW * IDIM];    // normalized theta
__device__ fp16  g_Mh[(size_t)BATCH * HW * DIM];     // attn out [b][n][c]
__device__ fp16  g_Wth[(size_t)DIM * DIM];           // W^T [d][c], 1 plane
__device__ fp16  g_PTh[(size_t)2 * IDIM * DIM];      // stacked [phi_w; theta_w]

// ---------------- helpers ----------------
__device__ __forceinline__ uint32_t smem_u32(const void* p) {
    uint32_t a;
    asm("{ .reg .u64 t; cvta.to.shared.u64 t, %1; cvt.u32.u64 %0, t; }" : "=r"(a) : "l"(p));
    return a;
}
__device__ __forceinline__ void cp16(uint32_t d, const void* s) {
    asm volatile("cp.async.cg.shared.global [%0], [%1], 16;" :: "r"(d), "l"(s));
}

#define LDSM4(R, addr)                                                           \
    asm volatile("ldmatrix.sync.aligned.m8n8.x4.shared.b16 {%0,%1,%2,%3}, [%4];" \
        : "=r"((R)[0]), "=r"((R)[1]), "=r"((R)[2]), "=r"((R)[3]) : "r"(addr))

#define MMA_FP16(c, a, b0, b1)                                                   \
    asm volatile(                                                                \
        "mma.sync.aligned.m16n8k16.row.col.f32.f16.f16.f32 "                     \
        "{%0,%1,%2,%3}, {%4,%5,%6,%7}, {%8,%9}, {%0,%1,%2,%3};"                  \
        : "+f"((c)[0]), "+f"((c)[1]), "+f"((c)[2]), "+f"((c)[3])                 \
        : "r"((a)[0]), "r"((a)[1]), "r"((a)[2]), "r"((a)[3]),                    \
          "r"((b0)), "r"((b1)))

// BK=32: rows are 64B (4 x 16B granules). granule q of row r stored at q ^ ((r>>1)&3).
__device__ __forceinline__ void fill_pl(uint32_t dbase, const fp16* src, int Kdim, int tid) {
    #pragma unroll
    for (int t = 0; t < 2; t++) {
        int idx = tid + t * 256;
        int row = idx >> 2, q = idx & 3;
        cp16(dbase + row * 64 + ((q ^ ((row >> 1) & 3)) << 4),
             src + (size_t)row * Kdim + q * 8);
    }
}

// ================= fp16 NT GEMM via mma.sync + ldmatrix =================
// C[m][n] = sum_k A[m][k]*B[n][k].  CTA 128x128, 8 warps (2x4) of 64x32,
// BK=32, 4-stage cp.async pipeline with prefetch distance 2 -> ONE
// __syncthreads per K-chunk (fill target last read two iterations ago).
// MODE 0: fp32 store   1: relu fp32 store
// MODE 3: exp2() + fp16 store + row partial sums (k2; Q pre-scaled by log2e)
// MODE 4: row scale by Inv + fp16 store (k4)
// MODE 5: fp16 store + row partial sum-of-squares (k1)
template<int MODE>
__global__ void __launch_bounds__(256) gemm_fp16(
    const fp16* __restrict__ A, const fp16* __restrict__ B,
    float* __restrict__ C, fp16* __restrict__ Ch,
    float* __restrict__ Part, const float* __restrict__ Inv,
    int Kdim, int Ncols, size_t sA, size_t sB, size_t sC)
{
    constexpr int SPS = 2 * 8192;     // stage bytes (A 8KB + B 8KB)
    extern __shared__ char smem[];
    const int tid  = threadIdx.x;
    const int lane = tid & 31, wid = tid >> 5;
    const int g = lane >> 2, tg = lane & 3;
    const int wm = wid >> 2, wn = wid & 3;
    const uint32_t sb = smem_u32(smem);

    const fp16* pA = A + blockIdx.z * sA + (size_t)blockIdx.y * 128 * Kdim;
    const fp16* pB = B + blockIdx.z * sB + (size_t)blockIdx.x * 128 * Kdim;

    float acc[4][4][4];
    #pragma unroll
    for (int i = 0; i < 4; i++)
        #pragma unroll
        for (int j = 0; j < 4; j++)
            #pragma unroll
            for (int e = 0; e < 4; e++) acc[i][j][e] = 0.f;

    const int NC = Kdim >> 5;
    const int rb = lane & 15, gs = lane >> 4;
    const int swz = (rb >> 1) & 3;

    // prologue: fill stages 0,1
    fill_pl(sb, pA, Kdim, tid);
    fill_pl(sb + 8192, pB, Kdim, tid);
    asm volatile("cp.async.commit_group;");
    fill_pl(sb + SPS, pA + 32, Kdim, tid);
    fill_pl(sb + SPS + 8192, pB + 32, Kdim, tid);
    asm volatile("cp.async.commit_group;");

    for (int c = 0; c < NC; c++) {
        if (c + 2 < NC) {
            uint32_t nb = sb + ((c + 2) & 3) * SPS;
            int ko = (c + 2) * 32;
            fill_pl(nb, pA + ko, Kdim, tid);
            fill_pl(nb + 8192, pB + ko, Kdim, tid);
            asm volatile("cp.async.commit_group;");
            asm volatile("cp.async.wait_group 2;");
        } else if (c + 2 == NC) {
            asm volatile("cp.async.wait_group 1;");
        } else {
            asm volatile("cp.async.wait_group 0;");
        }
        __syncthreads();   // the ONLY barrier per chunk

        uint32_t bb = sb + (c & 3) * SPS;
        #pragma unroll
        for (int s = 0; s < 2; s++) {
            const int gp = (((2 * s + gs) ^ swz) << 4);
            uint32_t af[4][4], bf[2][4];
            #pragma unroll
            for (int i = 0; i < 4; i++) {
                uint32_t ra = bb + (uint32_t)(wm * 64 + i * 16 + rb) * 64 + gp;
                LDSM4(af[i], ra);
            }
            #pragma unroll
            for (int t = 0; t < 2; t++) {
                uint32_t rba = bb + 8192 + (uint32_t)(wn * 32 + t * 16 + rb) * 64 + gp;
                LDSM4(bf[t], rba);
            }
            #pragma unroll
            for (int i = 0; i < 4; i++)
                #pragma unroll
                for (int j = 0; j < 4; j++) {
                    const int t = j >> 1, u = j & 1;
                    MMA_FP16(acc[i][j], af[i], bf[t][u], bf[t][u + 2]);
                }
        }
    }

    // ---------------- epilogue ----------------
    const int row0 = blockIdx.y * 128 + wm * 64;
    const int col0 = blockIdx.x * 128 + wn * 32;
    const int bz = blockIdx.z;

    if (MODE == 3 || MODE == 5) {
        __syncthreads();               // spart aliases stage 0
        float* spart = (float*)smem;   // [128][4]
        float rsum[4][2];
        #pragma unroll
        for (int i = 0; i < 4; i++) { rsum[i][0] = 0.f; rsum[i][1] = 0.f; }
        #pragma unroll
        for (int i = 0; i < 4; i++) {
            int r0 = row0 + i * 16 + g;
            #pragma unroll
            for (int j = 0; j < 4; j++) {
                int cc = col0 + j * 8 + tg * 2;
                float e0 = acc[i][j][0], e1 = acc[i][j][1];
                float e2 = acc[i][j][2], e3 = acc[i][j][3];
                if (MODE == 3) {
                    e0 = exp2f(e0); e1 = exp2f(e1);
                    e2 = exp2f(e2); e3 = exp2f(e3);
                    rsum[i][0] += e0 + e1;
                    rsum[i][1] += e2 + e3;
                } else {
                    rsum[i][0] += e0 * e0 + e1 * e1;
                    rsum[i][1] += e2 * e2 + e3 * e3;
                }
                size_t o0 = bz * sC + (size_t)r0 * Ncols + cc;
                size_t o1 = o0 + 8 * (size_t)Ncols;
                __half2 p0; p0.x = __float2half_rn(e0); p0.y = __float2half_rn(e1);
                __half2 p1; p1.x = __float2half_rn(e2); p1.y = __float2half_rn(e3);
                *reinterpret_cast<__half2*>(Ch + o0) = p0;
                *reinterpret_cast<__half2*>(Ch + o1) = p1;
            }
        }
        #pragma unroll
        for (int i = 0; i < 4; i++) {
            #pragma unroll
            for (int h = 0; h < 2; h++) {
                float v = rsum[i][h];
                v += __shfl_xor_sync(0xffffffffu, v, 1);
                v += __shfl_xor_sync(0xffffffffu, v, 2);
                if (tg == 0)
                    spart[(wm * 64 + i * 16 + g + h * 8) * 4 + wn] = v;
            }
        }
        __syncthreads();
        if (tid < 128) {
            float4 p = *reinterpret_cast<float4*>(spart + tid * 4);
            Part[((size_t)bz * HW + blockIdx.y * 128 + tid) * gridDim.x + blockIdx.x] =
                p.x + p.y + p.z + p.w;
        }
        return;
    }

    #pragma unroll
    for (int i = 0; i < 4; i++) {
        int r0 = row0 + i * 16 + g;
        float inv0 = 1.f, inv1 = 1.f;
        if (MODE == 4) {
            inv0 = Inv[(size_t)bz * HW + r0];
            inv1 = Inv[(size_t)bz * HW + r0 + 8];
        }
        #pragma unroll
        for (int j = 0; j < 4; j++) {
            int cc = col0 + j * 8 + tg * 2;
            if (MODE == 4) {
                size_t o0 = bz * sC + (size_t)r0 * Ncols + cc;
                size_t o1 = o0 + 8 * (size_t)Ncols;
                __half2 p0, p1;
                p0.x = __float2half_rn(acc[i][j][0] * inv0);
                p0.y = __float2half_rn(acc[i][j][1] * inv0);
                p1.x = __float2half_rn(acc[i][j][2] * inv1);
                p1.y = __float2half_rn(acc[i][j][3] * inv1);
                *reinterpret_cast<__half2*>(Ch + o0) = p0;
                *reinterpret_cast<__half2*>(Ch + o1) = p1;
            } else {
                float* b0 = C + bz * sC + (size_t)r0 * Ncols + cc;
                float* b1 = b0 + 8 * (size_t)Ncols;
                float2 v0, v1;
                v0.x = acc[i][j][0]; v0.y = acc[i][j][1];
                v1.x = acc[i][j][2]; v1.y = acc[i][j][3];
                if (MODE == 1) {
                    v0.x = fmaxf(v0.x, 0.f); v0.y = fmaxf(v0.y, 0.f);
                    v1.x = fmaxf(v1.x, 0.f); v1.y = fmaxf(v1.y, 0.f);
                }
                *reinterpret_cast<float2*>(b0) = v0;
                *reinterpret_cast<float2*>(b1) = v1;
            }
        }
    }
}

// ---------------- inv rowsum (k2 partials, stride 32) ----------------
__global__ void __launch_bounds__(256) k3b_inv() {
    int wid = threadIdx.x >> 5, lane = threadIdx.x & 31;
    size_t rr = (size_t)blockIdx.x * 8 + wid;
    float v = g_part[rr * 32 + lane];
    #pragma unroll
    for (int o = 16; o > 0; o >>= 1) v += __shfl_xor_sync(0xffffffffu, v, o);
    if (lane == 0) g_inv[rr] = 1.0f / v;
}

// ---------------- normalize QKh rows -> Qh (x log2e), Kh (4 partials) ----------------
__global__ void __launch_bounds__(256) k1d_scale() {
    size_t row = blockIdx.x;
    __shared__ float sinv[2];
    int t = threadIdx.x;
    if (t == 0) {
        const float* p = g_part + row * 4;
        sinv[0] = rsqrtf(p[0] + p[1]) * 1.4426950408889634f;  // phi: fold log2e
        sinv[1] = rsqrtf(p[2] + p[3]);                        // theta
    }
    __syncthreads();
    float s = sinv[t >> 7];
    __half2 v = reinterpret_cast<const __half2*>(g_QKh)[row * 256 + t];
    float2 f = __half22float2(v);
    __half2 r;
    r.x = __float2half_rn(f.x * s);
    r.y = __float2half_rn(f.y * s);
    if (t < 128)
        reinterpret_cast<__half2*>(g_Qh)[row * 128 + t] = r;
    else
        reinterpret_cast<__half2*>(g_Kh)[row * 128 + (t - 128)] = r;
}

// ---------------- feat -> Fth (transposed fp16) + Fh (straight fp16), one read ----------------
__global__ void __launch_bounds__(256) trans_dual(const float* __restrict__ in,
                                                  fp16* __restrict__ oth,
                                                  fp16* __restrict__ ostr,
                                                  int R, int C) {
    __shared__ float t[32][33];
    int b = blockIdx.z;
    const float* ib = in + (size_t)b * R * C;
    size_t ob = (size_t)b * R * C;
    int c0 = blockIdx.x * 32, r0 = blockIdx.y * 32;
    int x = threadIdx.x, y = threadIdx.y;
    #pragma unroll
    for (int i = 0; i < 32; i += 8) {
        float v = ib[(size_t)(r0 + y + i) * C + c0 + x];
        t[y + i][x] = v;
        ostr[ob + (size_t)(r0 + y + i) * C + c0 + x] = __float2half_rn(v);
    }
    __syncthreads();
    #pragma unroll
    for (int i = 0; i < 32; i += 8)
        oth[ob + (size_t)(c0 + y + i) * R + r0 + x] = __float2half_rn(t[x][y + i]);
}

// ---------------- transpose, 1-plane fp16 ----------------
__global__ void __launch_bounds__(256) trans1(const float* __restrict__ in,
                                              fp16* __restrict__ oh, int R, int C) {
    __shared__ float t[32][33];
    int b = blockIdx.z;
    const float* ib = in + (size_t)b * R * C;
    size_t ob = (size_t)b * R * C;
    int c0 = blockIdx.x * 32, r0 = blockIdx.y * 32;
    int x = threadIdx.x, y = threadIdx.y;
    #pragma unroll
    for (int i = 0; i < 32; i += 8)
        t[y + i][x] = ib[(size_t)(r0 + y + i) * C + c0 + x];
    __syncthreads();
    #pragma unroll
    for (int i = 0; i < 32; i += 8)
        oh[ob + (size_t)(c0 + y + i) * R + r0 + x] = __float2half_rn(t[x][y + i]);
}

// ---------------- elementwise fp16 conversion: [phi_w; theta_w] in one launch ----------------
__global__ void __launch_bounds__(256) conv_pt(const float* __restrict__ p,
                                               const float* __restrict__ t_,
                                               fp16* __restrict__ oh) {
    size_t half = (size_t)IDIM * DIM;          // 131072
    size_t i0 = ((size_t)blockIdx.x * 256 + threadIdx.x) * 4;
    const float* src = (i0 < half) ? p + i0 : t_ + (i0 - half);
    float4 v = *reinterpret_cast<const float4*>(src);
    __half2 a, b;
    a.x = __float2half_rn(v.x); a.y = __float2half_rn(v.y);
    b.x = __float2half_rn(v.z); b.y = __float2half_rn(v.w);
    *reinterpret_cast<__half2*>(oh + i0)     = a;
    *reinterpret_cast<__half2*>(oh + i0 + 2) = b;
}

// ---------------- launch ----------------
extern "C" void kernel_launch(void* const* d_in, const int* in_sizes, int n_in,
                              void* d_out, int out_size) {
    const float* feat    = (const float*)d_in[0];   // [8, 512, 64, 64]
    const float* phi_w   = (const float*)d_in[1];   // [256, 512]
    const float* theta_w = (const float*)d_in[2];   // [256, 512]
    const float* weight  = (const float*)d_in[3];   // [512, 512]
    float* out = (float*)d_out;                     // [8, 512, 64, 64]

    cudaFuncSetAttribute(gemm_fp16<5>, cudaFuncAttributeMaxDynamicSharedMemorySize, 4 * 16384);
    cudaFuncSetAttribute(gemm_fp16<3>, cudaFuncAttributeMaxDynamicSharedMemorySize, 4 * 16384);
    cudaFuncSetAttribute(gemm_fp16<4>, cudaFuncAttributeMaxDynamicSharedMemorySize, 4 * 16384);
    cudaFuncSetAttribute(gemm_fp16<1>, cudaFuncAttributeMaxDynamicSharedMemorySize, 4 * 16384);

    float *Part, *Inv;
    fp16 *QKh, *Eh, *Fth, *Fh, *Qh, *Kh, *Mh, *Wth, *PTh;
    cudaGetSymbolAddress((void**)&QKh,  g_QKh);
    cudaGetSymbolAddress((void**)&Part, g_part);
    cudaGetSymbolAddress((void**)&Inv,  g_inv);
    cudaGetSymbolAddress((void**)&Eh,   g_Eh);
    cudaGetSymbolAddress((void**)&Fth,  g_Fth);
    cudaGetSymbolAddress((void**)&Fh,   g_Fh);
    cudaGetSymbolAddress((void**)&Qh,   g_Qh);
    cudaGetSymbolAddress((void**)&Kh,   g_Kh);
    cudaGetSymbolAddress((void**)&Mh,   g_Mh);
    cudaGetSymbolAddress((void**)&Wth,  g_Wth);
    cudaGetSymbolAddress((void**)&PTh,  g_PTh);

    // prep: one pass over feat -> Fth + Fh; W^T; stacked projection weights (one launch)
    trans_dual<<<dim3(HW / 32, DIM / 32, BATCH), dim3(32, 8)>>>(feat, Fth, Fh, DIM, HW);
    trans1<<<dim3(DIM / 32, DIM / 32, 1), dim3(32, 8)>>>(weight, Wth, DIM, DIM);
    conv_pt<<<(2 * IDIM * DIM) / 1024, 256>>>(phi_w, theta_w, PTh);

    // k1: QKh[n][j] = Ft[n][:] . [phi_w;theta_w][j][:] + partial sumsq  (M=4096, N=512, K=512)
    gemm_fp16<5><<<dim3(512 / 128, HW / 128, BATCH), 256, 4 * 16384>>>(
        Fth, PTh, nullptr, QKh, Part, nullptr,
        DIM, 512, (size_t)HW * DIM, 0, (size_t)HW * 512);

    // normalize rows -> Qh (pre-scaled by log2e), Kh
    k1d_scale<<<BATCH * HW, 256>>>();

    // k2: E[n][m] = exp2(Qs . K) + row partial sums  (M=N=4096, K=256)
    gemm_fp16<3><<<dim3(HW / 128, HW / 128, BATCH), 256, 4 * 16384>>>(
        Qh, Kh, nullptr, Eh, Part, nullptr,
        IDIM, HW, (size_t)HW * IDIM, (size_t)HW * IDIM, (size_t)HW * HW);

    k3b_inv<<<HW * BATCH / 8, 256>>>();

    // k4: M[n][c] = (sum_m E[n][m] * F[c][m]) * inv[n]  (M=4096, N=512, K=4096)
    gemm_fp16<4><<<dim3(DIM / 128, HW / 128, BATCH), 256, 4 * 16384>>>(
        Eh, Fh, nullptr, Mh, nullptr, Inv,
        HW, DIM, (size_t)HW * HW, (size_t)DIM * HW, (size_t)HW * DIM);

    // k5: out[d][n] = relu(Wth[d][:] . Mh[n][:])   (M=512, N=4096, K=512)
    gemm_fp16<1><<<dim3(HW / 128, DIM / 128, BATCH), 256, 4 * 16384>>>(
        Wth, Mh, out, nullptr, nullptr, nullptr,
        DIM, HW, 0, (size_t)HW * DIM, (size_t)DIM * HW);
}